// round 17
// baseline (speedup 1.0000x reference)
#include <cuda_runtime.h>
#include <math.h>

// GaussianKernel: B=16, N=256, T=128, K=128, H=16
// phi(s) is scalar->R^16 => tabulate (TBL entries) + lerp from SMEM-resident table.

#define Bc 16
#define Nc 256
#define Tc 128
#define Kc 128
#define Hc 16
#define TBL 1024
#define MM_BLOCKS 1024
#define MM_THREADS 256
#define BUILD_BLOCKS 128
#define ENT_PER_BLK (TBL / BUILD_BLOCKS)    // 8
#define APPLY_BLOCKS 304
#define APPLY_THREADS 1024

__device__ unsigned g_dmin_part[MM_BLOCKS];
__device__ unsigned g_dmax_part[MM_BLOCKS];
__device__ unsigned g_gmin_part[MM_BLOCKS];
__device__ unsigned g_gmax_part[MM_BLOCKS];
__device__ unsigned g_bmin_part[MM_BLOCKS];
__device__ unsigned g_bmax_part[MM_BLOCKS];
__device__ float g_smin_f, g_scale_f;
__device__ __align__(16) float g_table[TBL * Hc];

// order-preserving float <-> uint encoding
__device__ __forceinline__ unsigned enc_f(float f) {
    unsigned u = __float_as_uint(f);
    return (u & 0x80000000u) ? ~u : (u | 0x80000000u);
}
__device__ __forceinline__ float dec_f(unsigned e) {
    unsigned u = (e & 0x80000000u) ? (e ^ 0x80000000u) : ~e;
    return __uint_as_float(u);
}

// nan_to_num(nan/inf/-inf -> 0), robust under --use_fast_math (no isfinite)
__device__ __forceinline__ float sanitize(float v) {
    unsigned u = __float_as_uint(v);
    return ((u & 0x7f800000u) == 0x7f800000u) ? 0.0f : v;
}

// int64 vs int32 token buffer detection (block-cooperative, blockDim >= 64)
__device__ __forceinline__ int detect_tok64(const int* __restrict__ tok) {
    int pred = (threadIdx.x < 64) ? (tok[2 * threadIdx.x + 1] == 0) : 1;
    return __syncthreads_and(pred);
}

// block reduce (min of emin, max of emax); result valid in thread 0
__device__ __forceinline__ void block_minmax(unsigned& emin, unsigned& emax,
                                             unsigned* smin_s, unsigned* smax_s) {
    #pragma unroll
    for (int o = 16; o > 0; o >>= 1) {
        emin = min(emin, __shfl_xor_sync(0xffffffffu, emin, o));
        emax = max(emax, __shfl_xor_sync(0xffffffffu, emax, o));
    }
    int w = threadIdx.x >> 5, l = threadIdx.x & 31;
    if (l == 0) { smin_s[w] = emin; smax_s[w] = emax; }
    __syncthreads();
    if (threadIdx.x == 0) {
        int nw = blockDim.x >> 5;
        for (int i = 1; i < nw; i++) {
            emin = min(emin, smin_s[i]);
            emax = max(emax, smax_s[i]);
        }
    }
}

__device__ __forceinline__ void mm4(float4 v, unsigned& lmin, unsigned& lmax, int san) {
    unsigned e;
    e = enc_f(san ? sanitize(v.x) : v.x); lmin = min(lmin, e); lmax = max(lmax, e);
    e = enc_f(san ? sanitize(v.y) : v.y); lmin = min(lmin, e); lmax = max(lmax, e);
    e = enc_f(san ? sanitize(v.z) : v.z); lmin = min(lmin, e); lmax = max(lmax, e);
    e = enc_f(san ? sanitize(v.w) : v.w); lmin = min(lmin, e); lmax = max(lmax, e);
}

// Coalesced scan, one float4 of d per thread (no loop), ~55 warps/SM.
__global__ void minmax_k(const float4* __restrict__ d4,
                         const float4* __restrict__ gamma4,
                         const float4* __restrict__ beta4) {
    __shared__ unsigned smin_s[8], smax_s[8];
    const int gb4 = (Tc * Tc) / 4;             // 4096 float4 per table
    const int per_blk = gb4 / MM_BLOCKS;       // 4

    unsigned dmin = 0xFFFFFFFFu, dmax = 0u;
    unsigned gmin = 0xFFFFFFFFu, gmax = 0u;
    unsigned bmin = 0xFFFFFFFFu, bmax = 0u;

    if (threadIdx.x < per_blk) {
        int i = blockIdx.x * per_blk + threadIdx.x;
        mm4(gamma4[i], gmin, gmax, 0);
        mm4(beta4[i],  bmin, bmax, 0);
    }
    mm4(d4[blockIdx.x * MM_THREADS + threadIdx.x], dmin, dmax, 1);

    block_minmax(dmin, dmax, smin_s, smax_s);
    if (threadIdx.x == 0) { g_dmin_part[blockIdx.x] = dmin; g_dmax_part[blockIdx.x] = dmax; }
    __syncthreads();
    block_minmax(gmin, gmax, smin_s, smax_s);
    if (threadIdx.x == 0) { g_gmin_part[blockIdx.x] = gmin; g_gmax_part[blockIdx.x] = gmax; }
    __syncthreads();
    block_minmax(bmin, bmax, smin_s, smax_s);
    if (threadIdx.x == 0) { g_bmin_part[blockIdx.x] = bmin; g_bmax_part[blockIdx.x] = bmax; }
}

// Reduce partials -> conservative s-bounds, then tabulate the exact network.
// W1/W2 staged in dynamic smem ONCE per block; 8 entries per block.
__global__ void build_k(const float* __restrict__ mu,
                        const float* __restrict__ log_sigma,
                        const float* __restrict__ W1,
                        const float* __restrict__ b1,
                        const float* __restrict__ W2,
                        const float* __restrict__ b2) {
    extern __shared__ float dyn_s[];
    float* sW1 = dyn_s;                         // 128*128
    float* sW2 = sW1 + Kc * Kc;                 // 128*16
    float* psi_s = sW2 + Kc * Hc;               // 8*128
    float* h_s = psi_s + ENT_PER_BLK * Kc;      // 8*128
    __shared__ float bounds_s[2];
    __shared__ unsigned smin_s[8], smax_s[8];
    const int j = threadIdx.x;                  // 0..127

    // stage W1/W2 (coalesced float4)
    {
        const float4* w1_4 = (const float4*)W1;
        float4* s1_4 = (float4*)sW1;
        #pragma unroll
        for (int q = 0; q < (Kc * Kc / 4) / 128; q++)
            s1_4[j + q * 128] = w1_4[j + q * 128];
        const float4* w2_4 = (const float4*)W2;
        float4* s2_4 = (float4*)sW2;
        #pragma unroll
        for (int q = 0; q < (Kc * Hc / 4) / 128; q++)
            s2_4[j + q * 128] = w2_4[j + q * 128];
    }

    // reduce the 1024-entry partial arrays (8 per thread each)
    {
        unsigned dmin = 0xFFFFFFFFu, dmax = 0u;
        unsigned gmin = 0xFFFFFFFFu, gmax = 0u;
        unsigned bmin = 0xFFFFFFFFu, bmax = 0u;
        #pragma unroll
        for (int q = 0; q < MM_BLOCKS / 128; q++) {
            int i = j + q * 128;
            dmin = min(dmin, g_dmin_part[i]); dmax = max(dmax, g_dmax_part[i]);
            gmin = min(gmin, g_gmin_part[i]); gmax = max(gmax, g_gmax_part[i]);
            bmin = min(bmin, g_bmin_part[i]); bmax = max(bmax, g_bmax_part[i]);
        }
        block_minmax(dmin, dmax, smin_s, smax_s);
        __syncthreads();
        block_minmax(gmin, gmax, smin_s, smax_s);
        __syncthreads();
        block_minmax(bmin, bmax, smin_s, smax_s);
        if (j == 0) {
            float dlo = dec_f(dmin), dhi = dec_f(dmax);
            float glo = dec_f(gmin), ghi = dec_f(gmax);
            float blo = dec_f(bmin), bhi = dec_f(bmax);
            float p1 = glo * dlo, p2 = glo * dhi, p3 = ghi * dlo, p4 = ghi * dhi;
            float pmin = fminf(fminf(p1, p2), fminf(p3, p4));
            float pmax = fmaxf(fmaxf(p1, p2), fmaxf(p3, p4));
            float smin = pmin + blo;
            float smax = pmax + bhi;
            bounds_s[0] = smin;
            bounds_s[1] = smax;
            if (blockIdx.x == 0) {
                g_smin_f  = smin;
                g_scale_f = (float)(TBL - 1) / fmaxf(smax - smin, 1e-30f);
            }
        }
        __syncthreads();
    }
    const float smin = bounds_s[0];
    const float step = (bounds_s[1] - smin) * (1.0f / (float)(TBL - 1));

    float ls   = log_sigma[j];
    float sig  = fmaxf(ls, 0.0f) + log1pf(expf(-fabsf(ls))) + 1e-6f;  // softplus + eps
    float inv  = 1.0f / sig;
    float coef = 0.3989422804014327f * inv;   // 1/sqrt(2*pi) / sigma
    float muj  = mu[j];
    float b1j  = b1[j];

    const int e0 = blockIdx.x * ENT_PER_BLK;

    // psi for all 8 entries (thread j = component j)
    #pragma unroll
    for (int e = 0; e < ENT_PER_BLK; e++) {
        float s = fmaf((float)(e0 + e), step, smin);
        float x = (s - muj) * inv;
        psi_s[e * Kc + j] = expf(-0.5f * x * x) * coef;
    }
    __syncthreads();

    // h = relu(psi @ W1 + b1), thread j = hidden unit j, loop entries
    #pragma unroll
    for (int e = 0; e < ENT_PER_BLK; e++) {
        float a0 = b1j, a1 = 0.0f;
        const float* pe = psi_s + e * Kc;
        #pragma unroll 8
        for (int k = 0; k < Kc; k += 2) {
            a0 = fmaf(pe[k],     sW1[k * Kc + j],       a0);
            a1 = fmaf(pe[k + 1], sW1[(k + 1) * Kc + j], a1);
        }
        h_s[e * Kc + j] = fmaxf(a0 + a1, 0.0f);
    }
    __syncthreads();

    // phi: thread j -> entry j>>4, output j&15 (all 128 threads busy)
    {
        int e = j >> 4, o = j & 15;
        float p0 = b2[o], p1 = 0.0f;
        const float* he = h_s + e * Kc;
        #pragma unroll 8
        for (int k = 0; k < Kc; k += 2) {
            p0 = fmaf(he[k],     sW2[k * Hc + o],       p0);
            p1 = fmaf(he[k + 1], sW2[(k + 1) * Hc + o], p1);
        }
        g_table[(e0 + e) * Hc + o] = p0 + p1;
    }
}

// SMEM bank-swizzle: 16B chunk c of row i lives at float4 index i*4 + (c ^ ((i>>2)&3)).
__device__ __forceinline__ int sw_idx(int i, int c) {
    return (i << 2) + (c ^ ((i >> 2) & 3));
}

// 2 blocks/SM (64 KB smem each), 64 warps/SM. Chunk-pair lerp keeps regs <= 32.
__global__ void __launch_bounds__(APPLY_THREADS, 2)
apply_k(const float* __restrict__ d,
        const int* __restrict__ tok,
        const float* __restrict__ gamma_t,
        const float* __restrict__ beta_t,
        float* __restrict__ out) {
    extern __shared__ float4 tbl4[];
    const int tid = threadIdx.x;
    const int is64 = detect_tok64(tok);

    const float4* gt4 = reinterpret_cast<const float4*>(g_table);
    for (int j = tid; j < TBL * 4; j += APPLY_THREADS) {
        int i = j >> 2, c = j & 3;
        tbl4[sw_idx(i, c)] = gt4[j];
    }
    __syncthreads();

    const float smin  = g_smin_f;
    const float scale = g_scale_f;
    const int total = Bc * Nc * Nc;

    for (int idx = blockIdx.x * APPLY_THREADS + tid; idx < total;
         idx += gridDim.x * APPLY_THREADS) {
        int m = idx & (Nc - 1);
        int n = (idx >> 8) & (Nc - 1);
        int b = idx >> 16;
        int ti = is64 ? tok[2 * (b * Nc + n)] : tok[b * Nc + n];
        int tj = is64 ? tok[2 * (b * Nc + m)] : tok[b * Nc + m];
        float g  = gamma_t[ti * Tc + tj];
        float be = beta_t[ti * Tc + tj];
        float dv = sanitize(d[idx]);
        float s = fmaf(g, dv, be);

        float t = fminf(fmaxf((s - smin) * scale, 0.0f), (float)(TBL - 1));
        int i0 = (int)t;
        if (i0 > TBL - 2) i0 = TBL - 2;
        float f = t - (float)i0;
        int i1 = i0 + 1;

        float* po = out + ((size_t)b * (Hc * Nc * Nc) + (size_t)n * Nc + m);
        #pragma unroll
        for (int cp = 0; cp < 2; cp++) {
            int c0 = 2 * cp, c1 = 2 * cp + 1;
            float4 a0 = tbl4[sw_idx(i0, c0)];
            float4 e0 = tbl4[sw_idx(i1, c0)];
            float4 a1 = tbl4[sw_idx(i0, c1)];
            float4 e1 = tbl4[sw_idx(i1, c1)];
            __stcs(po + (size_t)(4 * c0 + 0) * (Nc * Nc), fmaf(f, e0.x - a0.x, a0.x));
            __stcs(po + (size_t)(4 * c0 + 1) * (Nc * Nc), fmaf(f, e0.y - a0.y, a0.y));
            __stcs(po + (size_t)(4 * c0 + 2) * (Nc * Nc), fmaf(f, e0.z - a0.z, a0.z));
            __stcs(po + (size_t)(4 * c0 + 3) * (Nc * Nc), fmaf(f, e0.w - a0.w, a0.w));
            __stcs(po + (size_t)(4 * c1 + 0) * (Nc * Nc), fmaf(f, e1.x - a1.x, a1.x));
            __stcs(po + (size_t)(4 * c1 + 1) * (Nc * Nc), fmaf(f, e1.y - a1.y, a1.y));
            __stcs(po + (size_t)(4 * c1 + 2) * (Nc * Nc), fmaf(f, e1.z - a1.z, a1.z));
            __stcs(po + (size_t)(4 * c1 + 3) * (Nc * Nc), fmaf(f, e1.w - a1.w, a1.w));
        }
    }
}

extern "C" void kernel_launch(void* const* d_in, const int* in_sizes, int n_in,
                              void* d_out, int out_size) {
    const float* d         = (const float*)d_in[0];
    const int*   tokens    = (const int*)d_in[1];   // int32 or int64 (auto-detected)
    const float* mu        = (const float*)d_in[2];
    const float* log_sigma = (const float*)d_in[3];
    const float* W1        = (const float*)d_in[4];
    const float* b1        = (const float*)d_in[5];
    const float* W2        = (const float*)d_in[6];
    const float* b2        = (const float*)d_in[7];
    const float* gamma_t   = (const float*)d_in[8];
    const float* beta_t    = (const float*)d_in[9];
    float* out = (float*)d_out;

    const int build_smem = (Kc * Kc + Kc * Hc + 2 * ENT_PER_BLK * Kc) * (int)sizeof(float);

    static int attr_done = 0;
    if (!attr_done) {
        cudaFuncSetAttribute(apply_k, cudaFuncAttributeMaxDynamicSharedMemorySize,
                             TBL * Hc * (int)sizeof(float));
        cudaFuncSetAttribute(build_k, cudaFuncAttributeMaxDynamicSharedMemorySize,
                             build_smem);
        attr_done = 1;
    }

    minmax_k<<<MM_BLOCKS, MM_THREADS>>>((const float4*)d,
                                        (const float4*)gamma_t,
                                        (const float4*)beta_t);
    build_k<<<BUILD_BLOCKS, 128, build_smem>>>(mu, log_sigma, W1, b1, W2, b2);
    apply_k<<<APPLY_BLOCKS, APPLY_THREADS, TBL * Hc * (int)sizeof(float)>>>(
        d, tokens, gamma_t, beta_t, out);
}